// round 13
// baseline (speedup 1.0000x reference)
#include <cuda_runtime.h>
#include <cuda_fp16.h>
#include <cstdint>

// ImplicitFunction: fp16 m16n8k16 mma.sync, 2-term static weight split
// (W*s = Whi + Wlo), dynamically range-scaled fp16 activations.
// Round-13: EXACT r9 skeleton (NT=256, 32 rows/warp, 1 CTA/SM, wf[8] cache,
// kt-major hi/lo MMA passes — the 309us config) with ONLY the validated
// cheap epilogue applied: s folded into weights at prep, tree-max +
// redux.sync.max + rcp.approx quantize. No structural changes.

#define NT 256
#define TILE_M 256          // 8 warps * 32 rows, 1 CTA/SM
#define NEG 0.2f
#define NLAYER 6

#define OFF_WF   0
#define WF_BYTES (NLAYER * 8 * 4 * 32 * 16)   // [l][nt][kt][lane]{hi0,hi1,lo0,lo1}
#define OFF_BH   (OFF_WF + WF_BYTES)
#define OFF_W0   (OFF_BH + 1536)
#define OFF_S0   (OFF_W0 + 768)
#define OFF_B0   (OFF_S0 + 256)
#define OFF_WO   (OFF_B0 + 256)
#define OFF_SOBO (OFF_WO + 256)
#define SMEM_BYTES (OFF_SOBO + 16)

__device__ __align__(16) uint32_t g_wfrag[NLAYER * 8 * 4 * 32 * 4];

static __device__ __forceinline__ float lrelu(float t) { return fmaxf(t, NEG * t); }

static __device__ __forceinline__ uint32_t pack_h2(float a, float b) {
    __half2 h = __floats2half2_rn(a, b);   // a -> low, b -> high
    return *(uint32_t*)&h;
}
static __device__ __forceinline__ float frcp(float x) {
    float r;
    asm("rcp.approx.f32 %0, %1;" : "=f"(r) : "f"(x));
    return r;
}
static __device__ __forceinline__ void mma_f16(float* c, const uint32_t* a,
                                               uint32_t b0, uint32_t b1) {
    asm volatile(
        "mma.sync.aligned.m16n8k16.row.col.f32.f16.f16.f32 "
        "{%0,%1,%2,%3}, {%4,%5,%6,%7}, {%8,%9}, {%0,%1,%2,%3};"
        : "+f"(c[0]), "+f"(c[1]), "+f"(c[2]), "+f"(c[3])
        : "r"(a[0]), "r"(a[1]), "r"(a[2]), "r"(a[3]), "r"(b0), "r"(b1));
}

// ---------------- prep: (W * diag(s)) -> fp16 hi/lo digits, B-fragment order ----------------
__global__ void prep_weights(const float* __restrict__ wh, const float* __restrict__ sh) {
    int t = blockIdx.x * blockDim.x + threadIdx.x;
    if (t >= NLAYER * 8 * 4 * 32) return;
    int lane = t & 31;
    int kt = (t >> 5) & 3;
    int nt = (t >> 7) & 7;
    int l = t >> 10;
    int k0 = kt * 16 + (lane & 3) * 2;
    int nn = nt * 8 + (lane >> 2);
    const float* W = wh + l * 4096;       // W[k][n] row-major
    float sv = sh[l * 64 + nn];
    float w0 = W[k0 * 64 + nn] * sv;
    float w1 = W[(k0 + 1) * 64 + nn] * sv;
    float w2 = W[(k0 + 8) * 64 + nn] * sv;
    float w3 = W[(k0 + 9) * 64 + nn] * sv;

    __half h0 = __float2half_rn(w0), h1 = __float2half_rn(w1);
    __half h2 = __float2half_rn(w2), h3 = __float2half_rn(w3);
    float l0 = w0 - __half2float(h0), l1 = w1 - __half2float(h1);
    float l2 = w2 - __half2float(h2), l3 = w3 - __half2float(h3);

    uint4 o;
    __half2 p01 = __halves2half2(h0, h1);
    __half2 p23 = __halves2half2(h2, h3);
    o.x = *(uint32_t*)&p01;
    o.y = *(uint32_t*)&p23;
    o.z = pack_h2(l0, l1);
    o.w = pack_h2(l2, l3);
    ((uint4*)g_wfrag)[t] = o;
}

__global__ __launch_bounds__(NT, 1)
void implicit_mlp_f16(const float* __restrict__ points,
                      const float* __restrict__ w0,
                      const float* __restrict__ s0,
                      const float* __restrict__ b0,
                      const float* __restrict__ bh,
                      const float* __restrict__ wo,
                      const float* __restrict__ so,
                      const float* __restrict__ bo,
                      float* __restrict__ out,
                      int n, int ntiles)
{
    extern __shared__ __align__(16) unsigned char smem[];

    const int tid = threadIdx.x;
    const int wid = tid >> 5;
    const int lane = tid & 31;
    const int tig = lane & 3;
    const int grp = lane >> 2;
    const int cb = tig * 2;
    const unsigned rmask = 0xFu << (lane & ~3);

    {
        const uint4* gsrc = (const uint4*)g_wfrag;
        uint4* gdst = (uint4*)(smem + OFF_WF);
        for (int i = tid; i < WF_BYTES / 16; i += NT) gdst[i] = gsrc[i];
        float* d;
        d = (float*)(smem + OFF_BH); for (int i = tid; i < 384; i += NT) d[i] = bh[i];
        d = (float*)(smem + OFF_W0); for (int i = tid; i < 192; i += NT) d[i] = w0[i];
        d = (float*)(smem + OFF_S0); if (tid < 64) d[tid] = s0[tid];
        d = (float*)(smem + OFF_B0); if (tid < 64) d[tid] = b0[tid];
        d = (float*)(smem + OFF_WO); if (tid < 64) d[tid] = wo[tid];
        if (tid == 0) {
            ((float*)(smem + OFF_SOBO))[0] = so[0];
            ((float*)(smem + OFF_SOBO))[1] = bo[0];
        }
    }
    __syncthreads();

    const float* bh0    = (const float*)(smem + OFF_BH);
    const float* shm_w0 = (const float*)(smem + OFF_W0);
    const float* shm_s0 = (const float*)(smem + OFF_S0);
    const float* shm_b0 = (const float*)(smem + OFF_B0);
    const float* shm_wo = (const float*)(smem + OFF_WO);
    const float so_v = ((const float*)(smem + OFF_SOBO))[0];
    const float bo_v = ((const float*)(smem + OFF_SOBO))[1];
    const uint4* wf_sh = (const uint4*)(smem + OFF_WF);

    for (int tile = blockIdx.x; tile < ntiles; tile += gridDim.x) {
        const long long rowbase = (long long)tile * TILE_M + wid * 32;

        float acc[2][8][4];          // activations / accumulators (fp32)
        uint32_t A[2][4][4];         // fp16 A fragments (scaled)
        float rm[2][2];              // dequant scales [mt][rowhalf]

        // ---- layer 0 (K=3) scalar into acc ----
#pragma unroll
        for (int mt = 0; mt < 2; mt++) {
            const long long r0 = rowbase + mt * 16 + grp;
            const long long r1 = r0 + 8;
            float p0x = 0.f, p0y = 0.f, p0z = 0.f, p1x = 0.f, p1y = 0.f, p1z = 0.f;
            if (r0 < n) { p0x = points[r0*3+0]; p0y = points[r0*3+1]; p0z = points[r0*3+2]; }
            if (r1 < n) { p1x = points[r1*3+0]; p1y = points[r1*3+1]; p1z = points[r1*3+2]; }
#pragma unroll
            for (int nt = 0; nt < 8; nt++) {
#pragma unroll
                for (int j = 0; j < 2; j++) {
                    int c = nt * 8 + cb + j;
                    float wa = shm_w0[c], wb = shm_w0[64 + c], wc = shm_w0[128 + c];
                    float sv = shm_s0[c], bv = shm_b0[c];
                    acc[mt][nt][j]     = lrelu(fmaf(fmaf(p0x, wa, fmaf(p0y, wb, p0z * wc)), sv, bv));
                    acc[mt][nt][2 + j] = lrelu(fmaf(fmaf(p1x, wa, fmaf(p1y, wb, p1z * wc)), sv, bv));
                }
            }
        }

        // ---- 6 hidden layers ----
#pragma unroll
        for (int l = 0; l < NLAYER; l++) {
            // quantize: per (mt, rowhalf) scale, pack fp16 A fragments
#pragma unroll
            for (int mt = 0; mt < 2; mt++) {
                float p[8], q[8];
#pragma unroll
                for (int nt = 0; nt < 8; nt++) {
                    p[nt] = fmaxf(fabsf(acc[mt][nt][0]), fabsf(acc[mt][nt][1]));
                    q[nt] = fmaxf(fabsf(acc[mt][nt][2]), fabsf(acc[mt][nt][3]));
                }
                float m0 = fmaxf(fmaxf(fmaxf(p[0], p[1]), fmaxf(p[2], p[3])),
                                 fmaxf(fmaxf(p[4], p[5]), fmaxf(p[6], p[7])));
                float m1 = fmaxf(fmaxf(fmaxf(q[0], q[1]), fmaxf(q[2], q[3])),
                                 fmaxf(fmaxf(q[4], q[5]), fmaxf(q[6], q[7])));
                m0 = fmaxf(m0, 1e-30f);
                m1 = fmaxf(m1, 1e-30f);
                // positive fp32 bitpatterns are u32-order-isomorphic -> REDUX over 4-lane group
                m0 = __uint_as_float(__reduce_max_sync(rmask, __float_as_uint(m0)));
                m1 = __uint_as_float(__reduce_max_sync(rmask, __float_as_uint(m1)));
                rm[mt][0] = m0;
                rm[mt][1] = m1;
                float inv0 = frcp(m0), inv1 = frcp(m1);
#pragma unroll
                for (int kt = 0; kt < 4; kt++) {
                    A[mt][kt][0] = pack_h2(acc[mt][2*kt][0]   * inv0, acc[mt][2*kt][1]   * inv0);
                    A[mt][kt][1] = pack_h2(acc[mt][2*kt][2]   * inv1, acc[mt][2*kt][3]   * inv1);
                    A[mt][kt][2] = pack_h2(acc[mt][2*kt+1][0] * inv0, acc[mt][2*kt+1][1] * inv0);
                    A[mt][kt][3] = pack_h2(acc[mt][2*kt+1][2] * inv1, acc[mt][2*kt+1][3] * inv1);
                }
            }

            // MMA: 2 passes (Whi, Wlo), 16 independent MMAs per pass
#pragma unroll
            for (int mt = 0; mt < 2; mt++)
#pragma unroll
                for (int nt = 0; nt < 8; nt++)
#pragma unroll
                    for (int e = 0; e < 4; e++) acc[mt][nt][e] = 0.f;

            const uint4* wl = wf_sh + l * 1024 + lane;
#pragma unroll
            for (int kt = 0; kt < 4; kt++) {
                uint4 wf[8];
#pragma unroll
                for (int nt = 0; nt < 8; nt++) wf[nt] = wl[(nt * 4 + kt) * 32];
#pragma unroll
                for (int nt = 0; nt < 8; nt++) {
                    mma_f16(acc[0][nt], A[0][kt], wf[nt].x, wf[nt].y);   // W hi
                    mma_f16(acc[1][nt], A[1][kt], wf[nt].x, wf[nt].y);
                }
#pragma unroll
                for (int nt = 0; nt < 8; nt++) {
                    mma_f16(acc[0][nt], A[0][kt], wf[nt].z, wf[nt].w);   // W lo
                    mma_f16(acc[1][nt], A[1][kt], wf[nt].z, wf[nt].w);
                }
            }

            // dequant + bias + lrelu (s pre-folded into W), or fused output tail
            const float* bl = bh0 + l * 64;
            if (l < NLAYER - 1) {
#pragma unroll
                for (int mt = 0; mt < 2; mt++) {
                    float r0v = rm[mt][0], r1v = rm[mt][1];
#pragma unroll
                    for (int nt = 0; nt < 8; nt++) {
                        float2 bv = *(const float2*)(bl + nt * 8 + cb);
                        acc[mt][nt][0] = lrelu(fmaf(acc[mt][nt][0], r0v, bv.x));
                        acc[mt][nt][1] = lrelu(fmaf(acc[mt][nt][1], r0v, bv.y));
                        acc[mt][nt][2] = lrelu(fmaf(acc[mt][nt][2], r1v, bv.x));
                        acc[mt][nt][3] = lrelu(fmaf(acc[mt][nt][3], r1v, bv.y));
                    }
                }
            } else {
#pragma unroll
                for (int mt = 0; mt < 2; mt++) {
                    float r0v = rm[mt][0], r1v = rm[mt][1];
                    float d0 = 0.f, d1 = 0.f;
#pragma unroll
                    for (int nt = 0; nt < 8; nt++) {
                        float2 bv = *(const float2*)(bl + nt * 8 + cb);
                        float2 wv = *(const float2*)(shm_wo + nt * 8 + cb);
                        d0 = fmaf(lrelu(fmaf(acc[mt][nt][0], r0v, bv.x)), wv.x, d0);
                        d0 = fmaf(lrelu(fmaf(acc[mt][nt][1], r0v, bv.y)), wv.y, d0);
                        d1 = fmaf(lrelu(fmaf(acc[mt][nt][2], r1v, bv.x)), wv.x, d1);
                        d1 = fmaf(lrelu(fmaf(acc[mt][nt][3], r1v, bv.y)), wv.y, d1);
                    }
                    d0 += __shfl_xor_sync(0xffffffffu, d0, 1);
                    d0 += __shfl_xor_sync(0xffffffffu, d0, 2);
                    d1 += __shfl_xor_sync(0xffffffffu, d1, 1);
                    d1 += __shfl_xor_sync(0xffffffffu, d1, 2);
                    if (tig == 0) {
                        long long r0 = rowbase + mt * 16 + grp;
                        long long r1 = r0 + 8;
                        if (r0 < n) out[r0] = fmaf(d0, so_v, bo_v);
                        if (r1 < n) out[r1] = fmaf(d1, so_v, bo_v);
                    }
                }
            }
        }
    }
}

extern "C" void kernel_launch(void* const* d_in, const int* in_sizes, int n_in,
                              void* d_out, int out_size)
{
    const float* points = (const float*)d_in[0];
    const float* w0     = (const float*)d_in[1];
    const float* s0     = (const float*)d_in[2];
    const float* b0     = (const float*)d_in[3];
    const float* wh     = (const float*)d_in[4];
    const float* sh     = (const float*)d_in[5];
    const float* bh     = (const float*)d_in[6];
    const float* wo     = (const float*)d_in[7];
    const float* so     = (const float*)d_in[8];
    const float* bo     = (const float*)d_in[9];
    float* out = (float*)d_out;

    const int n = in_sizes[0] / 3;
    const int ntiles = (n + TILE_M - 1) / TILE_M;

    prep_weights<<<(NLAYER * 8 * 4 * 32 + 255) / 256, 256>>>(wh, sh);

    int sms = 148;
    cudaDeviceGetAttribute(&sms, cudaDevAttrMultiProcessorCount, 0);
    cudaFuncSetAttribute(implicit_mlp_f16,
                         cudaFuncAttributeMaxDynamicSharedMemorySize, SMEM_BYTES);
    int grid = sms < ntiles ? sms : ntiles;

    implicit_mlp_f16<<<grid, NT, SMEM_BYTES>>>(
        points, w0, s0, b0, bh, wo, so, bo, out, n, ntiles);
}

// round 14
// speedup vs baseline: 1.9139x; 1.9139x over previous
#include <cuda_runtime.h>
#include <cuda_fp16.h>
#include <cstdint>

// ImplicitFunction: fp16 m16n8k16 mma.sync, 2-term static weight split,
// dynamically range-scaled fp16 activations. Round-14 = the 309us round-9
// kernel byte-for-byte EXCEPT the per-layer scale s is folded into the
// weights at prep (W' = W*diag(s)), deleting the s loads and one multiply
// per element from every hidden epilogue. The round-9 quantizer (serial
// fmax chain + shfl.xor reduction + fp32 divide) is kept untouched — the
// redux/tree-max variant regressed codegen in rounds 10-13.

#define NT 256
#define TILE_M 256          // 8 warps * 32 rows, 1 CTA/SM
#define NEG 0.2f
#define NLAYER 6

#define OFF_WF   0
#define WF_BYTES (NLAYER * 8 * 4 * 32 * 16)   // [l][nt][kt][lane]{hi0,hi1,lo0,lo1}
#define OFF_BH   (OFF_WF + WF_BYTES)
#define OFF_W0   (OFF_BH + 1536)
#define OFF_S0   (OFF_W0 + 768)
#define OFF_B0   (OFF_S0 + 256)
#define OFF_WO   (OFF_B0 + 256)
#define OFF_SOBO (OFF_WO + 256)
#define SMEM_BYTES (OFF_SOBO + 16)

__device__ __align__(16) uint32_t g_wfrag[NLAYER * 8 * 4 * 32 * 4];

static __device__ __forceinline__ float lrelu(float t) { return fmaxf(t, NEG * t); }

static __device__ __forceinline__ uint32_t pack_h2(float a, float b) {
    __half2 h = __floats2half2_rn(a, b);   // a -> low, b -> high
    return *(uint32_t*)&h;
}

static __device__ __forceinline__ void mma_f16(float* c, const uint32_t* a,
                                               uint32_t b0, uint32_t b1) {
    asm volatile(
        "mma.sync.aligned.m16n8k16.row.col.f32.f16.f16.f32 "
        "{%0,%1,%2,%3}, {%4,%5,%6,%7}, {%8,%9}, {%0,%1,%2,%3};"
        : "+f"(c[0]), "+f"(c[1]), "+f"(c[2]), "+f"(c[3])
        : "r"(a[0]), "r"(a[1]), "r"(a[2]), "r"(a[3]), "r"(b0), "r"(b1));
}

// ---------------- prep: (W * diag(s)) -> fp16 hi/lo digits, B-fragment order ----------------
__global__ void prep_weights(const float* __restrict__ wh, const float* __restrict__ sh) {
    int t = blockIdx.x * blockDim.x + threadIdx.x;
    if (t >= NLAYER * 8 * 4 * 32) return;
    int lane = t & 31;
    int kt = (t >> 5) & 3;
    int nt = (t >> 7) & 7;
    int l = t >> 10;
    int k0 = kt * 16 + (lane & 3) * 2;
    int nn = nt * 8 + (lane >> 2);
    const float* W = wh + l * 4096;       // W[k][n] row-major
    float sv = sh[l * 64 + nn];
    float w0 = W[k0 * 64 + nn] * sv;
    float w1 = W[(k0 + 1) * 64 + nn] * sv;
    float w2 = W[(k0 + 8) * 64 + nn] * sv;
    float w3 = W[(k0 + 9) * 64 + nn] * sv;

    __half h0 = __float2half_rn(w0), h1 = __float2half_rn(w1);
    __half h2 = __float2half_rn(w2), h3 = __float2half_rn(w3);
    float l0 = w0 - __half2float(h0), l1 = w1 - __half2float(h1);
    float l2 = w2 - __half2float(h2), l3 = w3 - __half2float(h3);

    uint4 o;
    __half2 p01 = __halves2half2(h0, h1);
    __half2 p23 = __halves2half2(h2, h3);
    o.x = *(uint32_t*)&p01;
    o.y = *(uint32_t*)&p23;
    o.z = pack_h2(l0, l1);
    o.w = pack_h2(l2, l3);
    ((uint4*)g_wfrag)[t] = o;
}

__global__ __launch_bounds__(NT, 1)
void implicit_mlp_f16(const float* __restrict__ points,
                      const float* __restrict__ w0,
                      const float* __restrict__ s0,
                      const float* __restrict__ b0,
                      const float* __restrict__ bh,
                      const float* __restrict__ wo,
                      const float* __restrict__ so,
                      const float* __restrict__ bo,
                      float* __restrict__ out,
                      int n, int ntiles)
{
    extern __shared__ __align__(16) unsigned char smem[];

    const int tid = threadIdx.x;
    const int wid = tid >> 5;
    const int lane = tid & 31;
    const int tig = lane & 3;
    const int grp = lane >> 2;
    const int cb = tig * 2;

    {
        const uint4* gsrc = (const uint4*)g_wfrag;
        uint4* gdst = (uint4*)(smem + OFF_WF);
        for (int i = tid; i < WF_BYTES / 16; i += NT) gdst[i] = gsrc[i];
        float* d;
        d = (float*)(smem + OFF_BH); for (int i = tid; i < 384; i += NT) d[i] = bh[i];
        d = (float*)(smem + OFF_W0); for (int i = tid; i < 192; i += NT) d[i] = w0[i];
        d = (float*)(smem + OFF_S0); if (tid < 64) d[tid] = s0[tid];
        d = (float*)(smem + OFF_B0); if (tid < 64) d[tid] = b0[tid];
        d = (float*)(smem + OFF_WO); if (tid < 64) d[tid] = wo[tid];
        if (tid == 0) {
            ((float*)(smem + OFF_SOBO))[0] = so[0];
            ((float*)(smem + OFF_SOBO))[1] = bo[0];
        }
    }
    __syncthreads();

    const float* bh0    = (const float*)(smem + OFF_BH);
    const float* shm_w0 = (const float*)(smem + OFF_W0);
    const float* shm_s0 = (const float*)(smem + OFF_S0);
    const float* shm_b0 = (const float*)(smem + OFF_B0);
    const float* shm_wo = (const float*)(smem + OFF_WO);
    const float so_v = ((const float*)(smem + OFF_SOBO))[0];
    const float bo_v = ((const float*)(smem + OFF_SOBO))[1];
    const uint4* wf_sh = (const uint4*)(smem + OFF_WF);

    for (int tile = blockIdx.x; tile < ntiles; tile += gridDim.x) {
        const long long rowbase = (long long)tile * TILE_M + wid * 32;

        float acc[2][8][4];          // activations / accumulators (fp32)
        uint32_t A[2][4][4];         // fp16 A fragments (scaled)
        float rm[2][2];              // dequant scales [mt][rowhalf]

        // ---- layer 0 (K=3) scalar into acc ----
#pragma unroll
        for (int mt = 0; mt < 2; mt++) {
            const long long r0 = rowbase + mt * 16 + grp;
            const long long r1 = r0 + 8;
            float p0x = 0.f, p0y = 0.f, p0z = 0.f, p1x = 0.f, p1y = 0.f, p1z = 0.f;
            if (r0 < n) { p0x = points[r0*3+0]; p0y = points[r0*3+1]; p0z = points[r0*3+2]; }
            if (r1 < n) { p1x = points[r1*3+0]; p1y = points[r1*3+1]; p1z = points[r1*3+2]; }
#pragma unroll
            for (int nt = 0; nt < 8; nt++) {
#pragma unroll
                for (int j = 0; j < 2; j++) {
                    int c = nt * 8 + cb + j;
                    float wa = shm_w0[c], wb = shm_w0[64 + c], wc = shm_w0[128 + c];
                    float sv = shm_s0[c], bv = shm_b0[c];
                    acc[mt][nt][j]     = lrelu(fmaf(fmaf(p0x, wa, fmaf(p0y, wb, p0z * wc)), sv, bv));
                    acc[mt][nt][2 + j] = lrelu(fmaf(fmaf(p1x, wa, fmaf(p1y, wb, p1z * wc)), sv, bv));
                }
            }
        }

        // ---- 6 hidden layers ----
#pragma unroll
        for (int l = 0; l < NLAYER; l++) {
            // quantize: per (mt, rowhalf) scale, pack fp16 A fragments
            //           (round-9 codegen: serial fmax chain + shfl.xor + divide)
#pragma unroll
            for (int mt = 0; mt < 2; mt++) {
                float m0 = 0.f, m1 = 0.f;
#pragma unroll
                for (int nt = 0; nt < 8; nt++) {
                    m0 = fmaxf(m0, fmaxf(fabsf(acc[mt][nt][0]), fabsf(acc[mt][nt][1])));
                    m1 = fmaxf(m1, fmaxf(fabsf(acc[mt][nt][2]), fabsf(acc[mt][nt][3])));
                }
                m0 = fmaxf(m0, __shfl_xor_sync(0xffffffffu, m0, 1));
                m0 = fmaxf(m0, __shfl_xor_sync(0xffffffffu, m0, 2));
                m1 = fmaxf(m1, __shfl_xor_sync(0xffffffffu, m1, 1));
                m1 = fmaxf(m1, __shfl_xor_sync(0xffffffffu, m1, 2));
                m0 = fmaxf(m0, 1e-30f);
                m1 = fmaxf(m1, 1e-30f);
                rm[mt][0] = m0;
                rm[mt][1] = m1;
                float inv0 = 1.f / m0, inv1 = 1.f / m1;
#pragma unroll
                for (int kt = 0; kt < 4; kt++) {
                    A[mt][kt][0] = pack_h2(acc[mt][2*kt][0]   * inv0, acc[mt][2*kt][1]   * inv0);
                    A[mt][kt][1] = pack_h2(acc[mt][2*kt][2]   * inv1, acc[mt][2*kt][3]   * inv1);
                    A[mt][kt][2] = pack_h2(acc[mt][2*kt+1][0] * inv0, acc[mt][2*kt+1][1] * inv0);
                    A[mt][kt][3] = pack_h2(acc[mt][2*kt+1][2] * inv1, acc[mt][2*kt+1][3] * inv1);
                }
            }

            // MMA: 2 passes (Whi, Wlo), 16 independent MMAs per pass
#pragma unroll
            for (int mt = 0; mt < 2; mt++)
#pragma unroll
                for (int nt = 0; nt < 8; nt++)
#pragma unroll
                    for (int e = 0; e < 4; e++) acc[mt][nt][e] = 0.f;

            const uint4* wl = wf_sh + l * 1024 + lane;
#pragma unroll
            for (int kt = 0; kt < 4; kt++) {
                uint4 wf[8];
#pragma unroll
                for (int nt = 0; nt < 8; nt++) wf[nt] = wl[(nt * 4 + kt) * 32];
#pragma unroll
                for (int nt = 0; nt < 8; nt++) {
                    mma_f16(acc[0][nt], A[0][kt], wf[nt].x, wf[nt].y);   // W hi
                    mma_f16(acc[1][nt], A[1][kt], wf[nt].x, wf[nt].y);
                }
#pragma unroll
                for (int nt = 0; nt < 8; nt++) {
                    mma_f16(acc[0][nt], A[0][kt], wf[nt].z, wf[nt].w);   // W lo
                    mma_f16(acc[1][nt], A[1][kt], wf[nt].z, wf[nt].w);
                }
            }

            // dequant + bias + lrelu (s pre-folded into W), or fused output tail
            const float* bl = bh0 + l * 64;
            if (l < NLAYER - 1) {
#pragma unroll
                for (int mt = 0; mt < 2; mt++) {
                    float r0v = rm[mt][0], r1v = rm[mt][1];
#pragma unroll
                    for (int nt = 0; nt < 8; nt++) {
                        int c0 = nt * 8 + cb;
                        float b0v = bl[c0], b1v = bl[c0 + 1];
                        acc[mt][nt][0] = lrelu(fmaf(acc[mt][nt][0], r0v, b0v));
                        acc[mt][nt][1] = lrelu(fmaf(acc[mt][nt][1], r0v, b1v));
                        acc[mt][nt][2] = lrelu(fmaf(acc[mt][nt][2], r1v, b0v));
                        acc[mt][nt][3] = lrelu(fmaf(acc[mt][nt][3], r1v, b1v));
                    }
                }
            } else {
#pragma unroll
                for (int mt = 0; mt < 2; mt++) {
                    float r0v = rm[mt][0], r1v = rm[mt][1];
                    float d0 = 0.f, d1 = 0.f;
#pragma unroll
                    for (int nt = 0; nt < 8; nt++) {
                        int c0 = nt * 8 + cb;
                        float b0v = bl[c0], b1v = bl[c0 + 1];
                        float w0v = shm_wo[c0], w1v = shm_wo[c0 + 1];
                        d0 = fmaf(lrelu(fmaf(acc[mt][nt][0], r0v, b0v)), w0v, d0);
                        d0 = fmaf(lrelu(fmaf(acc[mt][nt][1], r0v, b1v)), w1v, d0);
                        d1 = fmaf(lrelu(fmaf(acc[mt][nt][2], r1v, b0v)), w0v, d1);
                        d1 = fmaf(lrelu(fmaf(acc[mt][nt][3], r1v, b1v)), w1v, d1);
                    }
                    d0 += __shfl_xor_sync(0xffffffffu, d0, 1);
                    d0 += __shfl_xor_sync(0xffffffffu, d0, 2);
                    d1 += __shfl_xor_sync(0xffffffffu, d1, 1);
                    d1 += __shfl_xor_sync(0xffffffffu, d1, 2);
                    if (tig == 0) {
                        long long r0 = rowbase + mt * 16 + grp;
                        long long r1 = r0 + 8;
                        if (r0 < n) out[r0] = fmaf(d0, so_v, bo_v);
                        if (r1 < n) out[r1] = fmaf(d1, so_v, bo_v);
                    }
                }
            }
        }
    }
}

extern "C" void kernel_launch(void* const* d_in, const int* in_sizes, int n_in,
                              void* d_out, int out_size)
{
    const float* points = (const float*)d_in[0];
    const float* w0     = (const float*)d_in[1];
    const float* s0     = (const float*)d_in[2];
    const float* b0     = (const float*)d_in[3];
    const float* wh     = (const float*)d_in[4];
    const float* sh     = (const float*)d_in[5];
    const float* bh     = (const float*)d_in[6];
    const float* wo     = (const float*)d_in[7];
    const float* so     = (const float*)d_in[8];
    const float* bo     = (const float*)d_in[9];
    float* out = (float*)d_out;

    const int n = in_sizes[0] / 3;
    const int ntiles = (n + TILE_M - 1) / TILE_M;

    prep_weights<<<(NLAYER * 8 * 4 * 32 + 255) / 256, 256>>>(wh, sh);

    int sms = 148;
    cudaDeviceGetAttribute(&sms, cudaDevAttrMultiProcessorCount, 0);
    cudaFuncSetAttribute(implicit_mlp_f16,
                         cudaFuncAttributeMaxDynamicSharedMemorySize, SMEM_BYTES);
    int grid = sms < ntiles ? sms : ntiles;

    implicit_mlp_f16<<<grid, NT, SMEM_BYTES>>>(
        points, w0, s0, b0, bh, wo, so, bo, out, n, ntiles);
}

// round 15
// speedup vs baseline: 1.9228x; 1.0047x over previous
#include <cuda_runtime.h>
#include <cuda_fp16.h>
#include <cstdint>

// ImplicitFunction: fp16 m16n8k16 mma.sync, 2-term static weight split
// (W*s = Whi + Wlo), dynamically range-scaled fp16 activations.
// Round-15: r14 numerics byte-for-byte, but the two m-tile streams per warp
// alternate r7-style within each layer:
//   mma(mt0,l) -> epi(mt1,l-1) -> mma(mt1,l) -> epi(mt0,l)
// so every epilogue issues while the other stream's HMMA burst drains.
// Same register state as r14 (acc[2][8][4], A[2][4][4], transient wf[8]) —
// no ping-pong buffers (the r10 mistake). Weight fragments are re-loaded per
// stream (2x weight LDS, modeled ~10% over the tensor pipe — acceptable).

#define NT 256
#define TILE_M 256          // 8 warps * 32 rows, 1 CTA/SM
#define NEG 0.2f
#define NLAYER 6

#define OFF_WF   0
#define WF_BYTES (NLAYER * 8 * 4 * 32 * 16)   // [l][nt][kt][lane]{hi0,hi1,lo0,lo1}
#define OFF_BH   (OFF_WF + WF_BYTES)
#define OFF_W0   (OFF_BH + 1536)
#define OFF_S0   (OFF_W0 + 768)
#define OFF_B0   (OFF_S0 + 256)
#define OFF_WO   (OFF_B0 + 256)
#define OFF_SOBO (OFF_WO + 256)
#define SMEM_BYTES (OFF_SOBO + 16)

__device__ __align__(16) uint32_t g_wfrag[NLAYER * 8 * 4 * 32 * 4];

static __device__ __forceinline__ float lrelu(float t) { return fmaxf(t, NEG * t); }

static __device__ __forceinline__ uint32_t pack_h2(float a, float b) {
    __half2 h = __floats2half2_rn(a, b);   // a -> low, b -> high
    return *(uint32_t*)&h;
}

static __device__ __forceinline__ void mma_f16(float* c, const uint32_t* a,
                                               uint32_t b0, uint32_t b1) {
    asm volatile(
        "mma.sync.aligned.m16n8k16.row.col.f32.f16.f16.f32 "
        "{%0,%1,%2,%3}, {%4,%5,%6,%7}, {%8,%9}, {%0,%1,%2,%3};"
        : "+f"(c[0]), "+f"(c[1]), "+f"(c[2]), "+f"(c[3])
        : "r"(a[0]), "r"(a[1]), "r"(a[2]), "r"(a[3]), "r"(b0), "r"(b1));
}

// ---------------- prep: (W * diag(s)) -> fp16 hi/lo digits, B-fragment order ----------------
__global__ void prep_weights(const float* __restrict__ wh, const float* __restrict__ sh) {
    int t = blockIdx.x * blockDim.x + threadIdx.x;
    if (t >= NLAYER * 8 * 4 * 32) return;
    int lane = t & 31;
    int kt = (t >> 5) & 3;
    int nt = (t >> 7) & 7;
    int l = t >> 10;
    int k0 = kt * 16 + (lane & 3) * 2;
    int nn = nt * 8 + (lane >> 2);
    const float* W = wh + l * 4096;       // W[k][n] row-major
    float sv = sh[l * 64 + nn];
    float w0 = W[k0 * 64 + nn] * sv;
    float w1 = W[(k0 + 1) * 64 + nn] * sv;
    float w2 = W[(k0 + 8) * 64 + nn] * sv;
    float w3 = W[(k0 + 9) * 64 + nn] * sv;

    __half h0 = __float2half_rn(w0), h1 = __float2half_rn(w1);
    __half h2 = __float2half_rn(w2), h3 = __float2half_rn(w3);
    float l0 = w0 - __half2float(h0), l1 = w1 - __half2float(h1);
    float l2 = w2 - __half2float(h2), l3 = w3 - __half2float(h3);

    uint4 o;
    __half2 p01 = __halves2half2(h0, h1);
    __half2 p23 = __halves2half2(h2, h3);
    o.x = *(uint32_t*)&p01;
    o.y = *(uint32_t*)&p23;
    o.z = pack_h2(l0, l1);
    o.w = pack_h2(l2, l3);
    ((uint4*)g_wfrag)[t] = o;
}

// ---------------- device helpers (r14 codegen idioms, untouched) ----------------
// quantize 32 post-activation values -> fp16 A fragments + per-rowhalf scales
static __device__ __forceinline__ void quantize_mt(
    const float (&o)[8][4], float& r0, float& r1, uint32_t (&A)[4][4])
{
    float m0 = 0.f, m1 = 0.f;
#pragma unroll
    for (int nt = 0; nt < 8; nt++) {
        m0 = fmaxf(m0, fmaxf(fabsf(o[nt][0]), fabsf(o[nt][1])));
        m1 = fmaxf(m1, fmaxf(fabsf(o[nt][2]), fabsf(o[nt][3])));
    }
    m0 = fmaxf(m0, __shfl_xor_sync(0xffffffffu, m0, 1));
    m0 = fmaxf(m0, __shfl_xor_sync(0xffffffffu, m0, 2));
    m1 = fmaxf(m1, __shfl_xor_sync(0xffffffffu, m1, 1));
    m1 = fmaxf(m1, __shfl_xor_sync(0xffffffffu, m1, 2));
    m0 = fmaxf(m0, 1e-30f);
    m1 = fmaxf(m1, 1e-30f);
    r0 = m0;
    r1 = m1;
    float inv0 = 1.f / m0, inv1 = 1.f / m1;
#pragma unroll
    for (int kt = 0; kt < 4; kt++) {
        A[kt][0] = pack_h2(o[2*kt][0]   * inv0, o[2*kt][1]   * inv0);
        A[kt][1] = pack_h2(o[2*kt][2]   * inv1, o[2*kt][3]   * inv1);
        A[kt][2] = pack_h2(o[2*kt+1][0] * inv0, o[2*kt+1][1] * inv0);
        A[kt][3] = pack_h2(o[2*kt+1][2] * inv1, o[2*kt+1][3] * inv1);
    }
}

// hidden-layer epilogue for one stream: dequant (s pre-folded) + bias + lrelu
// in place, then quantize for the next layer.
static __device__ __forceinline__ void epi_mt(
    float (&acc)[8][4], float& r0, float& r1,
    const float* bl, int cb, uint32_t (&A)[4][4])
{
    const float R0 = r0, R1 = r1;
#pragma unroll
    for (int nt = 0; nt < 8; nt++) {
        int c0 = nt * 8 + cb;
        float b0v = bl[c0], b1v = bl[c0 + 1];
        acc[nt][0] = lrelu(fmaf(acc[nt][0], R0, b0v));
        acc[nt][1] = lrelu(fmaf(acc[nt][1], R0, b1v));
        acc[nt][2] = lrelu(fmaf(acc[nt][2], R1, b0v));
        acc[nt][3] = lrelu(fmaf(acc[nt][3], R1, b1v));
    }
    quantize_mt(acc, r0, r1, A);
}

// one stream's MMA for one layer: zero acc; per k-tile load wf[8] and run
// the hi pass (8 independent MMAs) then the lo pass (dep distance 8).
static __device__ __forceinline__ void mma_stream(
    const uint4* wl, const uint32_t (&A)[4][4], float (&acc)[8][4])
{
#pragma unroll
    for (int nt = 0; nt < 8; nt++)
#pragma unroll
        for (int e = 0; e < 4; e++) acc[nt][e] = 0.f;
#pragma unroll
    for (int kt = 0; kt < 4; kt++) {
        uint4 wf[8];
#pragma unroll
        for (int nt = 0; nt < 8; nt++) wf[nt] = wl[(nt * 4 + kt) * 32];
#pragma unroll
        for (int nt = 0; nt < 8; nt++) mma_f16(acc[nt], A[kt], wf[nt].x, wf[nt].y);  // W hi
#pragma unroll
        for (int nt = 0; nt < 8; nt++) mma_f16(acc[nt], A[kt], wf[nt].z, wf[nt].w);  // W lo
    }
}

__global__ __launch_bounds__(NT, 1)
void implicit_mlp_f16(const float* __restrict__ points,
                      const float* __restrict__ w0,
                      const float* __restrict__ s0,
                      const float* __restrict__ b0,
                      const float* __restrict__ bh,
                      const float* __restrict__ wo,
                      const float* __restrict__ so,
                      const float* __restrict__ bo,
                      float* __restrict__ out,
                      int n, int ntiles)
{
    extern __shared__ __align__(16) unsigned char smem[];

    const int tid = threadIdx.x;
    const int wid = tid >> 5;
    const int lane = tid & 31;
    const int tig = lane & 3;
    const int grp = lane >> 2;
    const int cb = tig * 2;

    {
        const uint4* gsrc = (const uint4*)g_wfrag;
        uint4* gdst = (uint4*)(smem + OFF_WF);
        for (int i = tid; i < WF_BYTES / 16; i += NT) gdst[i] = gsrc[i];
        float* d;
        d = (float*)(smem + OFF_BH); for (int i = tid; i < 384; i += NT) d[i] = bh[i];
        d = (float*)(smem + OFF_W0); for (int i = tid; i < 192; i += NT) d[i] = w0[i];
        d = (float*)(smem + OFF_S0); if (tid < 64) d[tid] = s0[tid];
        d = (float*)(smem + OFF_B0); if (tid < 64) d[tid] = b0[tid];
        d = (float*)(smem + OFF_WO); if (tid < 64) d[tid] = wo[tid];
        if (tid == 0) {
            ((float*)(smem + OFF_SOBO))[0] = so[0];
            ((float*)(smem + OFF_SOBO))[1] = bo[0];
        }
    }
    __syncthreads();

    const float* bh0    = (const float*)(smem + OFF_BH);
    const float* shm_w0 = (const float*)(smem + OFF_W0);
    const float* shm_s0 = (const float*)(smem + OFF_S0);
    const float* shm_b0 = (const float*)(smem + OFF_B0);
    const float* shm_wo = (const float*)(smem + OFF_WO);
    const float so_v = ((const float*)(smem + OFF_SOBO))[0];
    const float bo_v = ((const float*)(smem + OFF_SOBO))[1];
    const uint4* wfp = (const uint4*)(smem + OFF_WF) + lane;

    for (int tile = blockIdx.x; tile < ntiles; tile += gridDim.x) {
        const long long rowbase = (long long)tile * TILE_M + wid * 32;

        float acc[2][8][4];          // per-stream activations / accumulators
        uint32_t A[2][4][4];         // per-stream fp16 A fragments (scaled)
        float rm[2][2];              // per-stream dequant scales [mt][rowhalf]

        // ---- layer 0 (K=3) scalar into acc (both streams) ----
#pragma unroll
        for (int mt = 0; mt < 2; mt++) {
            const long long r0 = rowbase + mt * 16 + grp;
            const long long r1 = r0 + 8;
            float p0x = 0.f, p0y = 0.f, p0z = 0.f, p1x = 0.f, p1y = 0.f, p1z = 0.f;
            if (r0 < n) { p0x = points[r0*3+0]; p0y = points[r0*3+1]; p0z = points[r0*3+2]; }
            if (r1 < n) { p1x = points[r1*3+0]; p1y = points[r1*3+1]; p1z = points[r1*3+2]; }
#pragma unroll
            for (int nt = 0; nt < 8; nt++) {
#pragma unroll
                for (int j = 0; j < 2; j++) {
                    int c = nt * 8 + cb + j;
                    float wa = shm_w0[c], wb = shm_w0[64 + c], wc = shm_w0[128 + c];
                    float sv = shm_s0[c], bv = shm_b0[c];
                    acc[mt][nt][j]     = lrelu(fmaf(fmaf(p0x, wa, fmaf(p0y, wb, p0z * wc)), sv, bv));
                    acc[mt][nt][2 + j] = lrelu(fmaf(fmaf(p1x, wa, fmaf(p1y, wb, p1z * wc)), sv, bv));
                }
            }
        }
        quantize_mt(acc[0], rm[0][0], rm[0][1], A[0]);

        // ---- 6 hidden layers, streams alternating:
        //      mma(mt0,l) -> epi(mt1,l-1) -> mma(mt1,l) -> epi(mt0,l) ----
#pragma unroll
        for (int l = 0; l < NLAYER; l++) {
            const uint4* wl = wfp + l * 1024;

            mma_stream(wl, A[0], acc[0]);

            if (l == 0) quantize_mt(acc[1], rm[1][0], rm[1][1], A[1]);
            else        epi_mt(acc[1], rm[1][0], rm[1][1], bh0 + (l - 1) * 64, cb, A[1]);

            mma_stream(wl, A[1], acc[1]);

            if (l < NLAYER - 1) {
                epi_mt(acc[0], rm[0][0], rm[0][1], bh0 + l * 64, cb, A[0]);
            } else {
                // ---- output tails (stream 0 overlaps stream 1's HMMA drain) ----
                const float* bl = bh0 + 5 * 64;
#pragma unroll
                for (int mt = 0; mt < 2; mt++) {
                    float r0v = rm[mt][0], r1v = rm[mt][1];
                    float d0 = 0.f, d1 = 0.f;
#pragma unroll
                    for (int nt = 0; nt < 8; nt++) {
                        int c0 = nt * 8 + cb;
                        float b0v = bl[c0], b1v = bl[c0 + 1];
                        float w0v = shm_wo[c0], w1v = shm_wo[c0 + 1];
                        d0 = fmaf(lrelu(fmaf(acc[mt][nt][0], r0v, b0v)), w0v, d0);
                        d0 = fmaf(lrelu(fmaf(acc[mt][nt][1], r0v, b1v)), w1v, d0);
                        d1 = fmaf(lrelu(fmaf(acc[mt][nt][2], r1v, b0v)), w0v, d1);
                        d1 = fmaf(lrelu(fmaf(acc[mt][nt][3], r1v, b1v)), w1v, d1);
                    }
                    d0 += __shfl_xor_sync(0xffffffffu, d0, 1);
                    d0 += __shfl_xor_sync(0xffffffffu, d0, 2);
                    d1 += __shfl_xor_sync(0xffffffffu, d1, 1);
                    d1 += __shfl_xor_sync(0xffffffffu, d1, 2);
                    if (tig == 0) {
                        long long r0 = rowbase + mt * 16 + grp;
                        long long r1 = r0 + 8;
                        if (r0 < n) out[r0] = fmaf(d0, so_v, bo_v);
                        if (r1 < n) out[r1] = fmaf(d1, so_v, bo_v);
                    }
                }
            }
        }
    }
}

extern "C" void kernel_launch(void* const* d_in, const int* in_sizes, int n_in,
                              void* d_out, int out_size)
{
    const float* points = (const float*)d_in[0];
    const float* w0     = (const float*)d_in[1];
    const float* s0     = (const float*)d_in[2];
    const float* b0     = (const float*)d_in[3];
    const float* wh     = (const float*)d_in[4];
    const float* sh     = (const float*)d_in[5];
    const float* bh     = (const float*)d_in[6];
    const float* wo     = (const float*)d_in[7];
    const float* so     = (const float*)d_in[8];
    const float* bo     = (const float*)d_in[9];
    float* out = (float*)d_out;

    const int n = in_sizes[0] / 3;
    const int ntiles = (n + TILE_M - 1) / TILE_M;

    prep_weights<<<(NLAYER * 8 * 4 * 32 + 255) / 256, 256>>>(wh, sh);

    int sms = 148;
    cudaDeviceGetAttribute(&sms, cudaDevAttrMultiProcessorCount, 0);
    cudaFuncSetAttribute(implicit_mlp_f16,
                         cudaFuncAttributeMaxDynamicSharedMemorySize, SMEM_BYTES);
    int grid = sms < ntiles ? sms : ntiles;

    implicit_mlp_f16<<<grid, NT, SMEM_BYTES>>>(
        points, w0, s0, b0, bh, wo, so, bo, out, n, ntiles);
}

// round 16
// speedup vs baseline: 2.3547x; 1.2246x over previous
#include <cuda_runtime.h>
#include <cuda_fp16.h>
#include <cstdint>

// ImplicitFunction: fp16 m16n8k16 mma.sync, 2-term static weight split
// (W*s = Whi + Wlo). Round-16: activations kept in a CONSTANT power-of-2
// scaled domain (x' = x * 2^-10) instead of dynamic per-row rmax scaling.
// lrelu is positively homogeneous, so the scale commutes through the whole
// network: C is folded into the staged layer-0 params and hidden biases
// (exact multiplies by 2^-10), and 1/C into the output scale. The hidden
// epilogue collapses to add + lrelu + pack — no max reduction, no shfl,
// no divide, no per-element muls. Skeleton = round-14 (295us, shared wf,
// kt-major MMA, 1 CTA/SM).

#define NT 256
#define TILE_M 256          // 8 warps * 32 rows, 1 CTA/SM
#define NEG 0.2f
#define NLAYER 6
#define CSCALE 0.0009765625f   // 2^-10 (exact)
#define CINV   1024.0f         // 2^10  (exact)

#define OFF_WF   0
#define WF_BYTES (NLAYER * 8 * 4 * 32 * 16)   // [l][nt][kt][lane]{hi0,hi1,lo0,lo1}
#define OFF_BH   (OFF_WF + WF_BYTES)
#define OFF_W0   (OFF_BH + 1536)
#define OFF_S0   (OFF_W0 + 768)
#define OFF_B0   (OFF_S0 + 256)
#define OFF_WO   (OFF_B0 + 256)
#define OFF_SOBO (OFF_WO + 256)
#define SMEM_BYTES (OFF_SOBO + 16)

__device__ __align__(16) uint32_t g_wfrag[NLAYER * 8 * 4 * 32 * 4];

static __device__ __forceinline__ float lrelu(float t) { return fmaxf(t, NEG * t); }

static __device__ __forceinline__ uint32_t pack_h2(float a, float b) {
    __half2 h = __floats2half2_rn(a, b);   // a -> low, b -> high
    return *(uint32_t*)&h;
}

static __device__ __forceinline__ void mma_f16(float* c, const uint32_t* a,
                                               uint32_t b0, uint32_t b1) {
    asm volatile(
        "mma.sync.aligned.m16n8k16.row.col.f32.f16.f16.f32 "
        "{%0,%1,%2,%3}, {%4,%5,%6,%7}, {%8,%9}, {%0,%1,%2,%3};"
        : "+f"(c[0]), "+f"(c[1]), "+f"(c[2]), "+f"(c[3])
        : "r"(a[0]), "r"(a[1]), "r"(a[2]), "r"(a[3]), "r"(b0), "r"(b1));
}

// ---------------- prep: (W * diag(s)) -> fp16 hi/lo digits, B-fragment order ----------------
__global__ void prep_weights(const float* __restrict__ wh, const float* __restrict__ sh) {
    int t = blockIdx.x * blockDim.x + threadIdx.x;
    if (t >= NLAYER * 8 * 4 * 32) return;
    int lane = t & 31;
    int kt = (t >> 5) & 3;
    int nt = (t >> 7) & 7;
    int l = t >> 10;
    int k0 = kt * 16 + (lane & 3) * 2;
    int nn = nt * 8 + (lane >> 2);
    const float* W = wh + l * 4096;       // W[k][n] row-major
    float sv = sh[l * 64 + nn];
    float w0 = W[k0 * 64 + nn] * sv;
    float w1 = W[(k0 + 1) * 64 + nn] * sv;
    float w2 = W[(k0 + 8) * 64 + nn] * sv;
    float w3 = W[(k0 + 9) * 64 + nn] * sv;

    __half h0 = __float2half_rn(w0), h1 = __float2half_rn(w1);
    __half h2 = __float2half_rn(w2), h3 = __float2half_rn(w3);
    float l0 = w0 - __half2float(h0), l1 = w1 - __half2float(h1);
    float l2 = w2 - __half2float(h2), l3 = w3 - __half2float(h3);

    uint4 o;
    __half2 p01 = __halves2half2(h0, h1);
    __half2 p23 = __halves2half2(h2, h3);
    o.x = *(uint32_t*)&p01;
    o.y = *(uint32_t*)&p23;
    o.z = pack_h2(l0, l1);
    o.w = pack_h2(l2, l3);
    ((uint4*)g_wfrag)[t] = o;
}

__global__ __launch_bounds__(NT, 1)
void implicit_mlp_f16(const float* __restrict__ points,
                      const float* __restrict__ w0,
                      const float* __restrict__ s0,
                      const float* __restrict__ b0,
                      const float* __restrict__ bh,
                      const float* __restrict__ wo,
                      const float* __restrict__ so,
                      const float* __restrict__ bo,
                      float* __restrict__ out,
                      int n, int ntiles)
{
    extern __shared__ __align__(16) unsigned char smem[];

    const int tid = threadIdx.x;
    const int wid = tid >> 5;
    const int lane = tid & 31;
    const int tig = lane & 3;
    const int grp = lane >> 2;
    const int cb = tig * 2;

    {
        const uint4* gsrc = (const uint4*)g_wfrag;
        uint4* gdst = (uint4*)(smem + OFF_WF);
        for (int i = tid; i < WF_BYTES / 16; i += NT) gdst[i] = gsrc[i];
        float* d;
        // hidden biases folded into the scaled domain: b' = b * C (exact)
        d = (float*)(smem + OFF_BH); for (int i = tid; i < 384; i += NT) d[i] = bh[i] * CSCALE;
        d = (float*)(smem + OFF_W0); for (int i = tid; i < 192; i += NT) d[i] = w0[i];
        // layer-0 scale/bias folded: s0' = s0*C, b0' = b0*C (exact)
        d = (float*)(smem + OFF_S0); if (tid < 64) d[tid] = s0[tid] * CSCALE;
        d = (float*)(smem + OFF_B0); if (tid < 64) d[tid] = b0[tid] * CSCALE;
        d = (float*)(smem + OFF_WO); if (tid < 64) d[tid] = wo[tid];
        if (tid == 0) {
            // output scale absorbs 1/C (exact)
            ((float*)(smem + OFF_SOBO))[0] = so[0] * CINV;
            ((float*)(smem + OFF_SOBO))[1] = bo[0];
        }
    }
    __syncthreads();

    const float* bh0    = (const float*)(smem + OFF_BH);
    const float* shm_w0 = (const float*)(smem + OFF_W0);
    const float* shm_s0 = (const float*)(smem + OFF_S0);
    const float* shm_b0 = (const float*)(smem + OFF_B0);
    const float* shm_wo = (const float*)(smem + OFF_WO);
    const float so_v = ((const float*)(smem + OFF_SOBO))[0];
    const float bo_v = ((const float*)(smem + OFF_SOBO))[1];
    const uint4* wf_sh = (const uint4*)(smem + OFF_WF);

    for (int tile = blockIdx.x; tile < ntiles; tile += gridDim.x) {
        const long long rowbase = (long long)tile * TILE_M + wid * 32;

        float acc[2][8][4];          // scaled-domain activations / accumulators
        uint32_t A[2][4][4];         // fp16 A fragments (scaled domain)

        // ---- layer 0 (K=3) scalar into acc, already in scaled domain ----
#pragma unroll
        for (int mt = 0; mt < 2; mt++) {
            const long long r0 = rowbase + mt * 16 + grp;
            const long long r1 = r0 + 8;
            float p0x = 0.f, p0y = 0.f, p0z = 0.f, p1x = 0.f, p1y = 0.f, p1z = 0.f;
            if (r0 < n) { p0x = points[r0*3+0]; p0y = points[r0*3+1]; p0z = points[r0*3+2]; }
            if (r1 < n) { p1x = points[r1*3+0]; p1y = points[r1*3+1]; p1z = points[r1*3+2]; }
#pragma unroll
            for (int nt = 0; nt < 8; nt++) {
#pragma unroll
                for (int j = 0; j < 2; j++) {
                    int c = nt * 8 + cb + j;
                    float wa = shm_w0[c], wb = shm_w0[64 + c], wc = shm_w0[128 + c];
                    float sv = shm_s0[c], bv = shm_b0[c];   // pre-scaled by C
                    acc[mt][nt][j]     = lrelu(fmaf(fmaf(p0x, wa, fmaf(p0y, wb, p0z * wc)), sv, bv));
                    acc[mt][nt][2 + j] = lrelu(fmaf(fmaf(p1x, wa, fmaf(p1y, wb, p1z * wc)), sv, bv));
                }
            }
        }

        // ---- 6 hidden layers ----
#pragma unroll
        for (int l = 0; l < NLAYER; l++) {
            // pack scaled-domain activations into fp16 A fragments (no scaling math)
#pragma unroll
            for (int mt = 0; mt < 2; mt++) {
#pragma unroll
                for (int kt = 0; kt < 4; kt++) {
                    A[mt][kt][0] = pack_h2(acc[mt][2*kt][0],   acc[mt][2*kt][1]);
                    A[mt][kt][1] = pack_h2(acc[mt][2*kt][2],   acc[mt][2*kt][3]);
                    A[mt][kt][2] = pack_h2(acc[mt][2*kt+1][0], acc[mt][2*kt+1][1]);
                    A[mt][kt][3] = pack_h2(acc[mt][2*kt+1][2], acc[mt][2*kt+1][3]);
                }
            }

            // MMA: 2 passes (Whi, Wlo), 16 independent MMAs per pass
#pragma unroll
            for (int mt = 0; mt < 2; mt++)
#pragma unroll
                for (int nt = 0; nt < 8; nt++)
#pragma unroll
                    for (int e = 0; e < 4; e++) acc[mt][nt][e] = 0.f;

            const uint4* wl = wf_sh + l * 1024 + lane;
#pragma unroll
            for (int kt = 0; kt < 4; kt++) {
                uint4 wf[8];
#pragma unroll
                for (int nt = 0; nt < 8; nt++) wf[nt] = wl[(nt * 4 + kt) * 32];
#pragma unroll
                for (int nt = 0; nt < 8; nt++) {
                    mma_f16(acc[0][nt], A[0][kt], wf[nt].x, wf[nt].y);   // W hi
                    mma_f16(acc[1][nt], A[1][kt], wf[nt].x, wf[nt].y);
                }
#pragma unroll
                for (int nt = 0; nt < 8; nt++) {
                    mma_f16(acc[0][nt], A[0][kt], wf[nt].z, wf[nt].w);   // W lo
                    mma_f16(acc[1][nt], A[1][kt], wf[nt].z, wf[nt].w);
                }
            }

            // epilogue: scaled-domain bias + lrelu (s folded into W, C into b)
            const float* bl = bh0 + l * 64;
            if (l < NLAYER - 1) {
#pragma unroll
                for (int mt = 0; mt < 2; mt++) {
#pragma unroll
                    for (int nt = 0; nt < 8; nt++) {
                        int c0 = nt * 8 + cb;
                        float b0v = bl[c0], b1v = bl[c0 + 1];
                        acc[mt][nt][0] = lrelu(acc[mt][nt][0] + b0v);
                        acc[mt][nt][1] = lrelu(acc[mt][nt][1] + b1v);
                        acc[mt][nt][2] = lrelu(acc[mt][nt][2] + b0v);
                        acc[mt][nt][3] = lrelu(acc[mt][nt][3] + b1v);
                    }
                }
            } else {
                // output tail: scaled dot; 1/C folded into so_v
#pragma unroll
                for (int mt = 0; mt < 2; mt++) {
                    float d0 = 0.f, d1 = 0.f;
#pragma unroll
                    for (int nt = 0; nt < 8; nt++) {
                        int c0 = nt * 8 + cb;
                        float b0v = bl[c0], b1v = bl[c0 + 1];
                        float w0v = shm_wo[c0], w1v = shm_wo[c0 + 1];
                        d0 = fmaf(lrelu(acc[mt][nt][0] + b0v), w0v, d0);
                        d0 = fmaf(lrelu(acc[mt][nt][1] + b1v), w1v, d0);
                        d1 = fmaf(lrelu(acc[mt][nt][2] + b0v), w0v, d1);
                        d1 = fmaf(lrelu(acc[mt][nt][3] + b1v), w1v, d1);
                    }
                    d0 += __shfl_xor_sync(0xffffffffu, d0, 1);
                    d0 += __shfl_xor_sync(0xffffffffu, d0, 2);
                    d1 += __shfl_xor_sync(0xffffffffu, d1, 1);
                    d1 += __shfl_xor_sync(0xffffffffu, d1, 2);
                    if (tig == 0) {
                        long long r0 = rowbase + mt * 16 + grp;
                        long long r1 = r0 + 8;
                        if (r0 < n) out[r0] = fmaf(d0, so_v, bo_v);
                        if (r1 < n) out[r1] = fmaf(d1, so_v, bo_v);
                    }
                }
            }
        }
    }
}

extern "C" void kernel_launch(void* const* d_in, const int* in_sizes, int n_in,
                              void* d_out, int out_size)
{
    const float* points = (const float*)d_in[0];
    const float* w0     = (const float*)d_in[1];
    const float* s0     = (const float*)d_in[2];
    const float* b0     = (const float*)d_in[3];
    const float* wh     = (const float*)d_in[4];
    const float* sh     = (const float*)d_in[5];
    const float* bh     = (const float*)d_in[6];
    const float* wo     = (const float*)d_in[7];
    const float* so     = (const float*)d_in[8];
    const float* bo     = (const float*)d_in[9];
    float* out = (float*)d_out;

    const int n = in_sizes[0] / 3;
    const int ntiles = (n + TILE_M - 1) / TILE_M;

    prep_weights<<<(NLAYER * 8 * 4 * 32 + 255) / 256, 256>>>(wh, sh);

    int sms = 148;
    cudaDeviceGetAttribute(&sms, cudaDevAttrMultiProcessorCount, 0);
    cudaFuncSetAttribute(implicit_mlp_f16,
                         cudaFuncAttributeMaxDynamicSharedMemorySize, SMEM_BYTES);
    int grid = sms < ntiles ? sms : ntiles;

    implicit_mlp_f16<<<grid, NT, SMEM_BYTES>>>(
        points, w0, s0, b0, bh, wo, so, bo, out, n, ntiles);
}

// round 17
// speedup vs baseline: 2.5031x; 1.0630x over previous
#include <cuda_runtime.h>
#include <cuda_fp16.h>
#include <cstdint>

// ImplicitFunction: fp16 m16n8k16 mma.sync, 2-term static weight split
// (W*s = Whi + Wlo), constant power-of-2 scaled activation domain (2^-10).
// Round-17 (on the 240us r16): two exact-cost epilogue cuts:
//   1. bias pre-loaded into the MMA accumulators (tensor core adds it)
//   2. LeakyReLU applied in fp16x2 AFTER the f32->half2 pack
// Hidden epilogue: 16 packs + 16 hmul2 + 16 hmax2 per m-tile. Output tail
// stays f32 (acc already contains bias).

#define NT 256
#define TILE_M 256          // 8 warps * 32 rows, 1 CTA/SM
#define NEG 0.2f
#define NLAYER 6
#define CSCALE 0.0009765625f   // 2^-10 (exact)
#define CINV   1024.0f         // 2^10  (exact)

#define OFF_WF   0
#define WF_BYTES (NLAYER * 8 * 4 * 32 * 16)   // [l][nt][kt][lane]{hi0,hi1,lo0,lo1}
#define OFF_BH   (OFF_WF + WF_BYTES)
#define OFF_W0   (OFF_BH + 1536)
#define OFF_S0   (OFF_W0 + 768)
#define OFF_B0   (OFF_S0 + 256)
#define OFF_WO   (OFF_B0 + 256)
#define OFF_SOBO (OFF_WO + 256)
#define SMEM_BYTES (OFF_SOBO + 16)

__device__ __align__(16) uint32_t g_wfrag[NLAYER * 8 * 4 * 32 * 4];

static __device__ __forceinline__ float lrelu(float t) { return fmaxf(t, NEG * t); }

static __device__ __forceinline__ uint32_t pack_h2(float a, float b) {
    __half2 h = __floats2half2_rn(a, b);   // a -> low, b -> high
    return *(uint32_t*)&h;
}

// fp16x2 LeakyReLU: max(h, 0.2*h) elementwise (exact for slope < 1)
static __device__ __forceinline__ uint32_t lrelu2(uint32_t h, __half2 neg2) {
    __half2 v = *(__half2*)&h;
    v = __hmax2(v, __hmul2(v, neg2));
    return *(uint32_t*)&v;
}

static __device__ __forceinline__ void mma_f16(float* c, const uint32_t* a,
                                               uint32_t b0, uint32_t b1) {
    asm volatile(
        "mma.sync.aligned.m16n8k16.row.col.f32.f16.f16.f32 "
        "{%0,%1,%2,%3}, {%4,%5,%6,%7}, {%8,%9}, {%0,%1,%2,%3};"
        : "+f"(c[0]), "+f"(c[1]), "+f"(c[2]), "+f"(c[3])
        : "r"(a[0]), "r"(a[1]), "r"(a[2]), "r"(a[3]), "r"(b0), "r"(b1));
}

// ---------------- prep: (W * diag(s)) -> fp16 hi/lo digits, B-fragment order ----------------
__global__ void prep_weights(const float* __restrict__ wh, const float* __restrict__ sh) {
    int t = blockIdx.x * blockDim.x + threadIdx.x;
    if (t >= NLAYER * 8 * 4 * 32) return;
    int lane = t & 31;
    int kt = (t >> 5) & 3;
    int nt = (t >> 7) & 7;
    int l = t >> 10;
    int k0 = kt * 16 + (lane & 3) * 2;
    int nn = nt * 8 + (lane >> 2);
    const float* W = wh + l * 4096;       // W[k][n] row-major
    float sv = sh[l * 64 + nn];
    float w0 = W[k0 * 64 + nn] * sv;
    float w1 = W[(k0 + 1) * 64 + nn] * sv;
    float w2 = W[(k0 + 8) * 64 + nn] * sv;
    float w3 = W[(k0 + 9) * 64 + nn] * sv;

    __half h0 = __float2half_rn(w0), h1 = __float2half_rn(w1);
    __half h2 = __float2half_rn(w2), h3 = __float2half_rn(w3);
    float l0 = w0 - __half2float(h0), l1 = w1 - __half2float(h1);
    float l2 = w2 - __half2float(h2), l3 = w3 - __half2float(h3);

    uint4 o;
    __half2 p01 = __halves2half2(h0, h1);
    __half2 p23 = __halves2half2(h2, h3);
    o.x = *(uint32_t*)&p01;
    o.y = *(uint32_t*)&p23;
    o.z = pack_h2(l0, l1);
    o.w = pack_h2(l2, l3);
    ((uint4*)g_wfrag)[t] = o;
}

__global__ __launch_bounds__(NT, 1)
void implicit_mlp_f16(const float* __restrict__ points,
                      const float* __restrict__ w0,
                      const float* __restrict__ s0,
                      const float* __restrict__ b0,
                      const float* __restrict__ bh,
                      const float* __restrict__ wo,
                      const float* __restrict__ so,
                      const float* __restrict__ bo,
                      float* __restrict__ out,
                      int n, int ntiles)
{
    extern __shared__ __align__(16) unsigned char smem[];

    const int tid = threadIdx.x;
    const int wid = tid >> 5;
    const int lane = tid & 31;
    const int tig = lane & 3;
    const int grp = lane >> 2;
    const int cb = tig * 2;
    const __half2 neg2 = __floats2half2_rn(NEG, NEG);

    {
        const uint4* gsrc = (const uint4*)g_wfrag;
        uint4* gdst = (uint4*)(smem + OFF_WF);
        for (int i = tid; i < WF_BYTES / 16; i += NT) gdst[i] = gsrc[i];
        float* d;
        // hidden biases folded into the scaled domain: b' = b * C (exact)
        d = (float*)(smem + OFF_BH); for (int i = tid; i < 384; i += NT) d[i] = bh[i] * CSCALE;
        d = (float*)(smem + OFF_W0); for (int i = tid; i < 192; i += NT) d[i] = w0[i];
        // layer-0 scale/bias folded: s0' = s0*C, b0' = b0*C (exact)
        d = (float*)(smem + OFF_S0); if (tid < 64) d[tid] = s0[tid] * CSCALE;
        d = (float*)(smem + OFF_B0); if (tid < 64) d[tid] = b0[tid] * CSCALE;
        d = (float*)(smem + OFF_WO); if (tid < 64) d[tid] = wo[tid];
        if (tid == 0) {
            ((float*)(smem + OFF_SOBO))[0] = so[0] * CINV;   // 1/C folded (exact)
            ((float*)(smem + OFF_SOBO))[1] = bo[0];
        }
    }
    __syncthreads();

    const float* bh0    = (const float*)(smem + OFF_BH);
    const float* shm_w0 = (const float*)(smem + OFF_W0);
    const float* shm_s0 = (const float*)(smem + OFF_S0);
    const float* shm_b0 = (const float*)(smem + OFF_B0);
    const float* shm_wo = (const float*)(smem + OFF_WO);
    const float so_v = ((const float*)(smem + OFF_SOBO))[0];
    const float bo_v = ((const float*)(smem + OFF_SOBO))[1];
    const uint4* wf_sh = (const uint4*)(smem + OFF_WF);

    for (int tile = blockIdx.x; tile < ntiles; tile += gridDim.x) {
        const long long rowbase = (long long)tile * TILE_M + wid * 32;

        float acc[2][8][4];          // scaled-domain accumulators (bias-initialized)
        uint32_t A[2][4][4];         // fp16 A fragments (scaled domain, post-lrelu)

        // ---- layer 0 (K=3) scalar, pack straight into A (lrelu in f32 here) ----
#pragma unroll
        for (int mt = 0; mt < 2; mt++) {
            const long long r0 = rowbase + mt * 16 + grp;
            const long long r1 = r0 + 8;
            float p0x = 0.f, p0y = 0.f, p0z = 0.f, p1x = 0.f, p1y = 0.f, p1z = 0.f;
            if (r0 < n) { p0x = points[r0*3+0]; p0y = points[r0*3+1]; p0z = points[r0*3+2]; }
            if (r1 < n) { p1x = points[r1*3+0]; p1y = points[r1*3+1]; p1z = points[r1*3+2]; }
            float o[8][4];
#pragma unroll
            for (int nt = 0; nt < 8; nt++) {
#pragma unroll
                for (int j = 0; j < 2; j++) {
                    int c = nt * 8 + cb + j;
                    float wa = shm_w0[c], wb = shm_w0[64 + c], wc = shm_w0[128 + c];
                    float sv = shm_s0[c], bv = shm_b0[c];   // pre-scaled by C
                    o[nt][j]     = lrelu(fmaf(fmaf(p0x, wa, fmaf(p0y, wb, p0z * wc)), sv, bv));
                    o[nt][2 + j] = lrelu(fmaf(fmaf(p1x, wa, fmaf(p1y, wb, p1z * wc)), sv, bv));
                }
            }
#pragma unroll
            for (int kt = 0; kt < 4; kt++) {
                A[mt][kt][0] = pack_h2(o[2*kt][0],   o[2*kt][1]);
                A[mt][kt][1] = pack_h2(o[2*kt][2],   o[2*kt][3]);
                A[mt][kt][2] = pack_h2(o[2*kt+1][0], o[2*kt+1][1]);
                A[mt][kt][3] = pack_h2(o[2*kt+1][2], o[2*kt+1][3]);
            }
        }

        // ---- 6 hidden layers ----
#pragma unroll
        for (int l = 0; l < NLAYER; l++) {
            const float* bl = bh0 + l * 64;

            // init accumulators with this layer's (scaled) bias — the tensor
            // core performs the bias add via the C operand.
#pragma unroll
            for (int mt = 0; mt < 2; mt++)
#pragma unroll
                for (int nt = 0; nt < 8; nt++) {
                    float2 bv = *(const float2*)(bl + nt * 8 + cb);
                    acc[mt][nt][0] = bv.x;
                    acc[mt][nt][1] = bv.y;
                    acc[mt][nt][2] = bv.x;
                    acc[mt][nt][3] = bv.y;
                }

            // MMA: 2 passes (Whi, Wlo), 16 independent MMAs per pass
            const uint4* wl = wf_sh + l * 1024 + lane;
#pragma unroll
            for (int kt = 0; kt < 4; kt++) {
                uint4 wf[8];
#pragma unroll
                for (int nt = 0; nt < 8; nt++) wf[nt] = wl[(nt * 4 + kt) * 32];
#pragma unroll
                for (int nt = 0; nt < 8; nt++) {
                    mma_f16(acc[0][nt], A[0][kt], wf[nt].x, wf[nt].y);   // W hi
                    mma_f16(acc[1][nt], A[1][kt], wf[nt].x, wf[nt].y);
                }
#pragma unroll
                for (int nt = 0; nt < 8; nt++) {
                    mma_f16(acc[0][nt], A[0][kt], wf[nt].z, wf[nt].w);   // W lo
                    mma_f16(acc[1][nt], A[1][kt], wf[nt].z, wf[nt].w);
                }
            }

            if (l < NLAYER - 1) {
                // epilogue: pack (bias already in acc), lrelu in fp16x2
#pragma unroll
                for (int mt = 0; mt < 2; mt++)
#pragma unroll
                    for (int kt = 0; kt < 4; kt++) {
                        A[mt][kt][0] = lrelu2(pack_h2(acc[mt][2*kt][0],   acc[mt][2*kt][1]),   neg2);
                        A[mt][kt][1] = lrelu2(pack_h2(acc[mt][2*kt][2],   acc[mt][2*kt][3]),   neg2);
                        A[mt][kt][2] = lrelu2(pack_h2(acc[mt][2*kt+1][0], acc[mt][2*kt+1][1]), neg2);
                        A[mt][kt][3] = lrelu2(pack_h2(acc[mt][2*kt+1][2], acc[mt][2*kt+1][3]), neg2);
                    }
            } else {
                // output tail in f32 (acc already contains bias)
#pragma unroll
                for (int mt = 0; mt < 2; mt++) {
                    float d0 = 0.f, d1 = 0.f;
#pragma unroll
                    for (int nt = 0; nt < 8; nt++) {
                        int c0 = nt * 8 + cb;
                        float w0v = shm_wo[c0], w1v = shm_wo[c0 + 1];
                        d0 = fmaf(lrelu(acc[mt][nt][0]), w0v, d0);
                        d0 = fmaf(lrelu(acc[mt][nt][1]), w1v, d0);
                        d1 = fmaf(lrelu(acc[mt][nt][2]), w0v, d1);
                        d1 = fmaf(lrelu(acc[mt][nt][3]), w1v, d1);
                    }
                    d0 += __shfl_xor_sync(0xffffffffu, d0, 1);
                    d0 += __shfl_xor_sync(0xffffffffu, d0, 2);
                    d1 += __shfl_xor_sync(0xffffffffu, d1, 1);
                    d1 += __shfl_xor_sync(0xffffffffu, d1, 2);
                    if (tig == 0) {
                        long long r0 = rowbase + mt * 16 + grp;
                        long long r1 = r0 + 8;
                        if (r0 < n) out[r0] = fmaf(d0, so_v, bo_v);
                        if (r1 < n) out[r1] = fmaf(d1, so_v, bo_v);
                    }
                }
            }
        }
    }
}

extern "C" void kernel_launch(void* const* d_in, const int* in_sizes, int n_in,
                              void* d_out, int out_size)
{
    const float* points = (const float*)d_in[0];
    const float* w0     = (const float*)d_in[1];
    const float* s0     = (const float*)d_in[2];
    const float* b0     = (const float*)d_in[3];
    const float* wh     = (const float*)d_in[4];
    const float* sh     = (const float*)d_in[5];
    const float* bh     = (const float*)d_in[6];
    const float* wo     = (const float*)d_in[7];
    const float* so     = (const float*)d_in[8];
    const float* bo     = (const float*)d_in[9];
    float* out = (float*)d_out;

    const int n = in_sizes[0] / 3;
    const int ntiles = (n + TILE_M - 1) / TILE_M;

    prep_weights<<<(NLAYER * 8 * 4 * 32 + 255) / 256, 256>>>(wh, sh);

    int sms = 148;
    cudaDeviceGetAttribute(&sms, cudaDevAttrMultiProcessorCount, 0);
    cudaFuncSetAttribute(implicit_mlp_f16,
                         cudaFuncAttributeMaxDynamicSharedMemorySize, SMEM_BYTES);
    int grid = sms < ntiles ? sms : ntiles;

    implicit_mlp_f16<<<grid, NT, SMEM_BYTES>>>(
        points, w0, s0, b0, bh, wo, so, bo, out, n, ntiles);
}